// round 2
// baseline (speedup 1.0000x reference)
#include <cuda_runtime.h>

// Problem dims (fixed by the dataset)
#define ZD 96
#define YD 96
#define XD 96
#define PL (YD * XD)          // 9216
#define VOL (ZD * YD * XD)    // 884736
#define CH 4
#define HS 3
#define KW 7

// Tiling
#define TX 32
#define TY 16
#define NT 512               // TX*TY threads
#define ZSEG 24
#define NZSEG 4              // 96 / ZSEG
#define XH (TX + 6)          // 38
#define SH (TY + 6)          // 22
#define SW 40                // padded row stride

// ---------------- persistent device scratch ----------------
__device__ float g_wlif[CH][KW];
__device__ float g_wq[CH][KW];
__device__ float g_slif[CH][ZD];    // boundary partial sums (conv_ones factor)
__device__ float g_u[CH * VOL];     // current u
__device__ float g_bufA[12 * VOL];  // [0..3]=Cn  [4..7]=Cn^2  [8..11]=q
__device__ float g_bufB[4 * VOL];   // logits a

// ---------------- setup ----------------
__global__ void k_setup(const float* __restrict__ sigma2,
                        const float* __restrict__ sigma3) {
    int c = threadIdx.x;
    if (c < CH) {
        float s2 = sigma2[c], s3 = sigma3[c];
        float w2[KW], w3[KW];
        float sum2 = 0.f, sum3 = 0.f;
        for (int t = 0; t < KW; t++) {
            float d = (float)(t - HS);
            w2[t] = expf(-d * d / (2.f * s2 * s2)); sum2 += w2[t];
            w3[t] = expf(-d * d / (2.f * s3 * s3)); sum3 += w3[t];
        }
        for (int t = 0; t < KW; t++) {
            g_wq[c][t]   = w2[t] / sum2;
            g_wlif[c][t] = w3[t] / sum3;
        }
        for (int p = 0; p < ZD; p++) {
            float s = 0.f;
            for (int t = 0; t < KW; t++) {
                int q = p + t - HS;
                if (q >= 0 && q < ZD) s += g_wlif[c][t];
            }
            g_slif[c][p] = s;
        }
    }
}

// ---------------- u0 = softmax(o / eta) ----------------
__global__ void k_init(const float* __restrict__ o,
                       const float* __restrict__ eta_p) {
    int i = blockIdx.x * blockDim.x + threadIdx.x;
    if (i >= VOL) return;
    float inv_eta = 1.f / eta_p[0];
    float a0 = o[i] * inv_eta;
    float a1 = o[VOL + i] * inv_eta;
    float a2 = o[2 * VOL + i] * inv_eta;
    float a3 = o[3 * VOL + i] * inv_eta;
    float m = fmaxf(fmaxf(a0, a1), fmaxf(a2, a3));
    float e0 = expf(a0 - m), e1 = expf(a1 - m), e2 = expf(a2 - m), e3 = expf(a3 - m);
    float inv = 1.f / (e0 + e1 + e2 + e3);
    g_u[i] = e0 * inv;
    g_u[VOL + i] = e1 * inv;
    g_u[2 * VOL + i] = e2 * inv;
    g_u[3 * VOL + i] = e3 * inv;
}

// ============ Kernel A: u,I -> Cn, Cn^2, q (full 3D separable conv, fused) ============
__global__ __launch_bounds__(NT, 2) void kA(const float* __restrict__ I) {
    const int c  = blockIdx.z >> 2;            // NZSEG == 4
    const int zs = (blockIdx.z & 3) * ZSEG;
    const int x0 = blockIdx.x * TX;
    const int y0 = blockIdx.y * TY;

    __shared__ float s0[SH][SW], s1[SH][SW], s2[SH][SW];  // raw: u*I, u, (1-2u)|valid
    __shared__ float t0[TY][SW], t1[TY][SW], t2[TY][SW];  // y-conved

    const int tid = threadIdx.x;
    const int tx = tid & (TX - 1);
    const int ty = tid >> 5;

    float wl[KW], wq[KW];
#pragma unroll
    for (int t = 0; t < KW; t++) { wl[t] = g_wlif[c][t]; wq[t] = g_wq[c][t]; }

    float r0[KW], r1[KW], r2[KW];
#pragma unroll
    for (int t = 0; t < KW; t++) { r0[t] = 0.f; r1[t] = 0.f; r2[t] = 0.f; }

    for (int s = zs - 3; s < zs + ZSEG + 3; ++s) {
        // shift ring
#pragma unroll
        for (int t = 0; t < KW - 1; t++) { r0[t] = r0[t+1]; r1[t] = r1[t+1]; r2[t] = r2[t+1]; }

        if (s >= 0 && s < ZD) {
            // load raw plane with halo (zero outside)
            for (int idx = tid; idx < SH * XH; idx += NT) {
                int yy = idx / XH;
                int xh = idx - yy * XH;
                int gy = y0 + yy - 3;
                int gx = x0 + xh - 3;
                float uv = 0.f, Iv = 0.f, wv = 0.f;
                if (gy >= 0 && gy < YD && gx >= 0 && gx < XD) {
                    int gi = s * PL + gy * XD + gx;
                    uv = g_u[c * VOL + gi];
                    Iv = I[gi];
                    wv = 1.f - 2.f * uv;
                }
                s0[yy][xh] = uv * Iv;
                s1[yy][xh] = uv;
                s2[yy][xh] = wv;
            }
            __syncthreads();
            // y-conv
            for (int idx = tid; idx < TY * XH; idx += NT) {
                int yo = idx / XH;
                int xh = idx - yo * XH;
                float a0 = 0.f, a1 = 0.f, a2 = 0.f;
#pragma unroll
                for (int t = 0; t < KW; t++) {
                    a0 += wl[t] * s0[yo + t][xh];
                    a1 += wl[t] * s1[yo + t][xh];
                    a2 += wq[t] * s2[yo + t][xh];
                }
                t0[yo][xh] = a0; t1[yo][xh] = a1; t2[yo][xh] = a2;
            }
            __syncthreads();
            // x-conv -> ring
            float v0 = 0.f, v1 = 0.f, v2 = 0.f;
#pragma unroll
            for (int t = 0; t < KW; t++) {
                v0 += wl[t] * t0[ty][tx + t];
                v1 += wl[t] * t1[ty][tx + t];
                v2 += wq[t] * t2[ty][tx + t];
            }
            r0[KW-1] = v0; r1[KW-1] = v1; r2[KW-1] = v2;
        } else {
            r0[KW-1] = 0.f; r1[KW-1] = 0.f; r2[KW-1] = 0.f;
        }

        // emit z = s - 3
        if (s >= zs + 3) {
            int z = s - 3;
            float C1 = 0.f, C2 = 0.f, Q = 0.f;
#pragma unroll
            for (int t = 0; t < KW; t++) {
                C1 += wl[t] * r0[t];
                C2 += wl[t] * r1[t];
                Q  += wq[t] * r2[t];
            }
            float Cn = (C1 + 1e-6f) / (C2 + 1e-6f);
            int i = z * PL + (y0 + ty) * XD + (x0 + tx);
            g_bufA[(0 * CH + c) * VOL + i] = Cn;
            g_bufA[(1 * CH + c) * VOL + i] = Cn * Cn;
            g_bufA[(2 * CH + c) * VOL + i] = Q;
        }
    }
}

// ============ Kernel B: Cn,Cn^2 -> conv -> Lif + q + o -> logits a ============
__global__ __launch_bounds__(NT, 2) void kB(const float* __restrict__ o,
                                            const float* __restrict__ I,
                                            const float* __restrict__ lam_p,
                                            const float* __restrict__ mu_p) {
    const int c  = blockIdx.z >> 2;
    const int zs = (blockIdx.z & 3) * ZSEG;
    const int x0 = blockIdx.x * TX;
    const int y0 = blockIdx.y * TY;

    __shared__ float sE[SH][SW], sD[SH][SW];
    __shared__ float tE[TY][SW], tD[TY][SW];

    const int tid = threadIdx.x;
    const int tx = tid & (TX - 1);
    const int ty = tid >> 5;

    const float lam = lam_p[0];
    const float mu  = mu_p[0];

    float wl[KW];
#pragma unroll
    for (int t = 0; t < KW; t++) wl[t] = g_wlif[c][t];

    float rE[KW], rD[KW];
#pragma unroll
    for (int t = 0; t < KW; t++) { rE[t] = 0.f; rD[t] = 0.f; }

    const float sy = g_slif[c][y0 + ty];
    const float sx = g_slif[c][x0 + tx];

    for (int s = zs - 3; s < zs + ZSEG + 3; ++s) {
#pragma unroll
        for (int t = 0; t < KW - 1; t++) { rE[t] = rE[t+1]; rD[t] = rD[t+1]; }

        if (s >= 0 && s < ZD) {
            for (int idx = tid; idx < SH * XH; idx += NT) {
                int yy = idx / XH;
                int xh = idx - yy * XH;
                int gy = y0 + yy - 3;
                int gx = x0 + xh - 3;
                float e = 0.f, d = 0.f;
                if (gy >= 0 && gy < YD && gx >= 0 && gx < XD) {
                    int gi = s * PL + gy * XD + gx;
                    e = g_bufA[(0 * CH + c) * VOL + gi];
                    d = g_bufA[(1 * CH + c) * VOL + gi];
                }
                sE[yy][xh] = e;
                sD[yy][xh] = d;
            }
            __syncthreads();
            for (int idx = tid; idx < TY * XH; idx += NT) {
                int yo = idx / XH;
                int xh = idx - yo * XH;
                float aE = 0.f, aD = 0.f;
#pragma unroll
                for (int t = 0; t < KW; t++) {
                    aE += wl[t] * sE[yo + t][xh];
                    aD += wl[t] * sD[yo + t][xh];
                }
                tE[yo][xh] = aE; tD[yo][xh] = aD;
            }
            __syncthreads();
            float vE = 0.f, vD = 0.f;
#pragma unroll
            for (int t = 0; t < KW; t++) {
                vE += wl[t] * tE[ty][tx + t];
                vD += wl[t] * tD[ty][tx + t];
            }
            rE[KW-1] = vE; rD[KW-1] = vD;
        } else {
            rE[KW-1] = 0.f; rD[KW-1] = 0.f;
        }

        if (s >= zs + 3) {
            int z = s - 3;
            float E = 0.f, D = 0.f;
#pragma unroll
            for (int t = 0; t < KW; t++) { E += wl[t] * rE[t]; D += wl[t] * rD[t]; }
            int i = z * PL + (y0 + ty) * XD + (x0 + tx);
            float Iv = I[i];
            float cones = g_slif[c][z] * sy * sx;
            float Lif = D - 2.f * Iv * E + Iv * Iv * cones;
            float q = g_bufA[(2 * CH + c) * VOL + i];
            g_bufB[c * VOL + i] = o[c * VOL + i] - mu * Lif - lam * q;
        }
    }
}

// ============ Kernel C: softmax(a / eta) ============
__global__ void kC(const float* __restrict__ eta_p, float* __restrict__ out,
                   int write_ext) {
    int i = blockIdx.x * blockDim.x + threadIdx.x;
    if (i >= VOL) return;
    float inv_eta = 1.f / eta_p[0];
    float a0 = g_bufB[i] * inv_eta;
    float a1 = g_bufB[VOL + i] * inv_eta;
    float a2 = g_bufB[2 * VOL + i] * inv_eta;
    float a3 = g_bufB[3 * VOL + i] * inv_eta;
    float m = fmaxf(fmaxf(a0, a1), fmaxf(a2, a3));
    float e0 = expf(a0 - m), e1 = expf(a1 - m), e2 = expf(a2 - m), e3 = expf(a3 - m);
    float inv = 1.f / (e0 + e1 + e2 + e3);
    float* dst = write_ext ? out : g_u;
    dst[i] = e0 * inv;
    dst[VOL + i] = e1 * inv;
    dst[2 * VOL + i] = e2 * inv;
    dst[3 * VOL + i] = e3 * inv;
}

// ---------------- launch ----------------
extern "C" void kernel_launch(void* const* d_in, const int* in_sizes, int n_in,
                              void* d_out, int out_size) {
    const float* o      = (const float*)d_in[0];
    const float* I      = (const float*)d_in[1];
    const float* sigma2 = (const float*)d_in[2];
    const float* sigma3 = (const float*)d_in[3];
    const float* eta    = (const float*)d_in[4];
    const float* lam    = (const float*)d_in[5];
    const float* mu     = (const float*)d_in[6];
    float* out = (float*)d_out;

    const int Tpt = 256;
    const int Bpt = (VOL + Tpt - 1) / Tpt;

    k_setup<<<1, 32>>>(sigma2, sigma3);
    k_init<<<Bpt, Tpt>>>(o, eta);

    dim3 grid(XD / TX, YD / TY, CH * NZSEG);  // (3, 6, 16)

    const int NB_ITERS = 10;
    for (int it = 0; it < NB_ITERS; ++it) {
        kA<<<grid, NT>>>(I);
        kB<<<grid, NT>>>(o, I, lam, mu);
        kC<<<Bpt, Tpt>>>(eta, out, (it == NB_ITERS - 1) ? 1 : 0);
    }
}